// round 1
// baseline (speedup 1.0000x reference)
#include <cuda_runtime.h>
#include <cstdint>

#define T_STEPS 4096
#define RES     2048
#define DIMS    64
#define NCTA    128
#define ROWS_PER_CTA 16   // RES / NCTA
#define THREADS_ESN  512

// ---------------- scratch (static device globals; no runtime allocs) ----------------
__device__ float g_U[(size_t)T_STEPS * DIMS];       // [t][d]
__device__ float g_G[(size_t)RES * T_STEPS];        // [r][t]  (W_in @ u_t, precomputed)
__device__ float g_H[(size_t)T_STEPS * RES];        // [t][r]  (reservoir states)
__device__ int   g_cnt[T_STEPS];                    // per-step arrive counters

// packed f32x2 FMA (Blackwell)
__device__ __forceinline__ unsigned long long ffma2(unsigned long long a,
                                                    unsigned long long b,
                                                    unsigned long long c) {
    unsigned long long d;
    asm("fma.rn.f32x2 %0, %1, %2, %3;" : "=l"(d) : "l"(a), "l"(b), "l"(c));
    return d;
}

// ---------------- kernel 1: U[t][d] = sum_i C[d][i] * X[t][i]; also zero counters ----
__global__ __launch_bounds__(256) void k_u(const float* __restrict__ X,
                                           const float* __restrict__ C) {
    __shared__ float Cs[64][65];
    __shared__ float xs[4][64];
    int tid = threadIdx.x;
    int b = blockIdx.x;
    for (int i = tid; i < 64 * 64; i += 256) Cs[i >> 6][i & 63] = C[i];
    int tl = tid >> 6, d = tid & 63;
    int t = b * 4 + tl;
    xs[tl][d] = X[t * 64 + d];
    __syncthreads();
    float acc = 0.f;
#pragma unroll
    for (int i = 0; i < 64; i++) acc = fmaf(Cs[d][i], xs[tl][i], acc);
    g_U[t * 64 + d] = acc;
    int gi = b * 256 + tid;
    if (gi < T_STEPS) g_cnt[gi] = 0;
}

// ---------------- kernel 2: G[r][t] = sum_d W_in[r][d] * U[t][d] --------------------
__global__ __launch_bounds__(512) void k_g(const float* __restrict__ Win) {
    __shared__ float Us[32][65];
    int tid = threadIdx.x, w = tid >> 5, l = tid & 31;
    int t0 = blockIdx.x * 32;
    for (int i = tid; i < 32 * 64; i += 512) Us[i >> 6][i & 63] = g_U[t0 * 64 + i];
    __syncthreads();
    for (int k = 0; k < 128; k++) {
        int r = w * 128 + k;
        const float* wrow = Win + r * 64;
        float acc = 0.f;
#pragma unroll
        for (int d = 0; d < 64; d++) acc = fmaf(__ldg(wrow + d), Us[l][d], acc);
        g_G[(size_t)r * T_STEPS + t0 + l] = acc;
    }
}

// ---------------- kernel 3: persistent reservoir recurrence -------------------------
// 128 CTAs x 512 threads. CTA c owns rows [16c, 16c+16) of W_res in registers.
// warp w covers column block [128w, 128w+128); lane l = (row = l>>1, half = l&1).
// Lane covers columns { 128w + 8j + 4*half + k : j in [0,16), k in [0,4) }.
__global__ __launch_bounds__(THREADS_ESN, 1) void k_esn(const float* __restrict__ Wres) {
    __shared__ __align__(16) float hsm[RES];
    __shared__ float parts[16][17];

    int tid = threadIdx.x, w = tid >> 5, l = tid & 31;
    int cta = blockIdx.x;
    int row = l >> 1, half = l & 1;
    int grow = cta * ROWS_PER_CTA + row;     // global row this lane accumulates
    int outrow = cta * ROWS_PER_CTA + w;     // global row this warp outputs

    // Load this lane's 64 W_res weights as 32 packed f32x2 operands.
    unsigned long long wreg[32];
    {
        const ulonglong2* wp = reinterpret_cast<const ulonglong2*>(
            Wres + (size_t)grow * RES + w * 128 + half * 4);
#pragma unroll
        for (int j = 0; j < 16; j++) {
            ulonglong2 v = wp[j * 2];        // 16B at float offset j*8
            wreg[2 * j]     = v.x;
            wreg[2 * j + 1] = v.y;
        }
    }

    for (int i = tid; i < RES; i += THREADS_ESN) hsm[i] = 0.f;
    __syncthreads();

    for (int t = 0; t < T_STEPS; t++) {
        // prefetch this warp's G value early (independent of h)
        float gval = (l == 0) ? __ldg(&g_G[(size_t)outrow * T_STEPS + t]) : 0.f;

        // partial dot over this lane's 64 columns (packed f32x2)
        const ulonglong2* hp = reinterpret_cast<const ulonglong2*>(
            hsm + w * 128 + half * 4);
        unsigned long long acc0 = 0ull, acc1 = 0ull;
#pragma unroll
        for (int j = 0; j < 16; j++) {
            ulonglong2 hv = hp[j * 2];       // LDS.128, 2 distinct addrs/warp: conflict-free
            acc0 = ffma2(wreg[2 * j],     hv.x, acc0);
            acc1 = ffma2(wreg[2 * j + 1], hv.y, acc1);
        }
        float s = __uint_as_float((unsigned)acc0) +
                  __uint_as_float((unsigned)(acc0 >> 32)) +
                  __uint_as_float((unsigned)acc1) +
                  __uint_as_float((unsigned)(acc1 >> 32));
        s += __shfl_xor_sync(0xffffffffu, s, 1);        // combine the two halves
        if (half == 0) parts[row][w] = s;
        __syncthreads();

        // warp w reduces row w across the 16 warps' column blocks
        float v = (l < 16) ? parts[w][l] : 0.f;
#pragma unroll
        for (int o = 8; o; o >>= 1) v += __shfl_xor_sync(0xffffffffu, v, o);

        if (l == 0) {
            float hv = tanhf(v + gval);
            g_H[(size_t)t * RES + outrow] = hv;
            __threadfence();                 // release: make h visible before arrive
        }
        __syncthreads();

        if (tid == 0) {
            atomicAdd(&g_cnt[t], 1);
            volatile int* vc = g_cnt + t;
            while (*vc < NCTA) { }
            __threadfence();                 // acquire
        }
        __syncthreads();

        if (t + 1 < T_STEPS) {
            // reload full h_t into SMEM, bypassing L1 (remote SMs wrote it)
            float4 hv = __ldcg(reinterpret_cast<const float4*>(g_H + (size_t)t * RES) + tid);
            reinterpret_cast<float4*>(hsm)[tid] = hv;
            __syncthreads();
        }
    }
}

// ---------------- kernel 4: y[t] = dW[0:64].U[t] + dW[64:].H[t] + b ------------------
__global__ __launch_bounds__(256) void k_out(const float* __restrict__ dW,
                                             const float* __restrict__ db,
                                             float* __restrict__ y) {
    int t = blockIdx.x, tid = threadIdx.x;
    float acc = 0.f;
    if (tid < 64) acc = dW[tid] * g_U[t * 64 + tid];
    for (int r = tid; r < RES; r += 256)
        acc = fmaf(dW[64 + r], g_H[(size_t)t * RES + r], acc);
#pragma unroll
    for (int o = 16; o; o >>= 1) acc += __shfl_xor_sync(0xffffffffu, acc, o);
    __shared__ float red[8];
    if ((tid & 31) == 0) red[tid >> 5] = acc;
    __syncthreads();
    if (tid < 8) {
        float v = red[tid];
        v += __shfl_xor_sync(0xffu, v, 4);
        v += __shfl_xor_sync(0xffu, v, 2);
        v += __shfl_xor_sync(0xffu, v, 1);
        if (tid == 0) y[t] = v + db[0];
    }
}

// ---------------- launcher ----------------------------------------------------------
extern "C" void kernel_launch(void* const* d_in, const int* in_sizes, int n_in,
                              void* d_out, int out_size) {
    const float* X    = (const float*)d_in[0];   // (4096, 64, 1)
    const float* C    = (const float*)d_in[1];   // (64, 64)
    const float* Win  = (const float*)d_in[2];   // (2048, 64)
    const float* Wres = (const float*)d_in[3];   // (2048, 2048)
    const float* dW   = (const float*)d_in[4];   // (1, 2112)
    const float* db   = (const float*)d_in[5];   // (1,)
    float* y = (float*)d_out;                    // (4096, 1, 1)

    k_u  <<<T_STEPS / 4, 256>>>(X, C);           // also zeroes g_cnt
    k_g  <<<T_STEPS / 32, 512>>>(Win);
    k_esn<<<NCTA, THREADS_ESN>>>(Wres);
    k_out<<<T_STEPS, 256>>>(dW, db, y);
}

// round 2
// speedup vs baseline: 2.0363x; 2.0363x over previous
#include <cuda_runtime.h>
#include <cstdint>

#define T_STEPS 4096
#define RES     2048
#define DIMS    64
#define NCTA    128
#define ROWS_PER_CTA 16   // RES / NCTA
#define THREADS_ESN  512
#define NGROUPS 1024      // RES/2 groups of {h0,h1,tag,pad}

// ---------------- scratch (static device globals; no runtime allocs) ----------------
__device__ float g_U[(size_t)T_STEPS * DIMS];        // [t][d]
__device__ float g_G[(size_t)RES * T_STEPS];         // [r][t]  (W_in @ u_t, precomputed)
__device__ float g_H[(size_t)T_STEPS * RES];         // [t][r]  (reservoir states, for k_out)
__device__ __align__(16) unsigned int g_buf[2][NGROUPS * 4];  // [parity][group*4] = {h0,h1,tag,pad}

// packed f32x2 FMA (Blackwell)
__device__ __forceinline__ unsigned long long ffma2(unsigned long long a,
                                                    unsigned long long b,
                                                    unsigned long long c) {
    unsigned long long d;
    asm("fma.rn.f32x2 %0, %1, %2, %3;" : "=l"(d) : "l"(a), "l"(b), "l"(c));
    return d;
}

// ---------------- kernel 1: U[t][d] = C@x_t; also zero the exchange buffers ---------
__global__ __launch_bounds__(256) void k_u(const float* __restrict__ X,
                                           const float* __restrict__ C) {
    __shared__ float Cs[64][65];
    __shared__ float xs[4][64];
    int tid = threadIdx.x;
    int b = blockIdx.x;
    for (int i = tid; i < 64 * 64; i += 256) Cs[i >> 6][i & 63] = C[i];
    int tl = tid >> 6, d = tid & 63;
    int t = b * 4 + tl;
    xs[tl][d] = X[t * 64 + d];
    __syncthreads();
    float acc = 0.f;
#pragma unroll
    for (int i = 0; i < 64; i++) acc = fmaf(Cs[d][i], xs[tl][i], acc);
    g_U[t * 64 + d] = acc;
    // zero both parity buffers (2 * 1024 * 4 = 8192 ints) so stale tags never match
    int gi = b * 256 + tid;
    if (gi < 2 * NGROUPS * 4) ((unsigned int*)g_buf)[gi] = 0u;
}

// ---------------- kernel 2: G[r][t] = sum_d W_in[r][d] * U[t][d] --------------------
__global__ __launch_bounds__(512) void k_g(const float* __restrict__ Win) {
    __shared__ float Us[32][65];
    int tid = threadIdx.x, w = tid >> 5, l = tid & 31;
    int t0 = blockIdx.x * 32;
    for (int i = tid; i < 32 * 64; i += 512) Us[i >> 6][i & 63] = g_U[t0 * 64 + i];
    __syncthreads();
    for (int k = 0; k < 128; k++) {
        int r = w * 128 + k;
        const float* wrow = Win + r * 64;
        float acc = 0.f;
#pragma unroll
        for (int d = 0; d < 64; d++) acc = fmaf(__ldg(wrow + d), Us[l][d], acc);
        g_G[(size_t)r * T_STEPS + t0 + l] = acc;
    }
}

// ---------------- kernel 3: persistent reservoir recurrence -------------------------
// 128 CTAs x 512 threads. CTA c owns rows [16c, 16c+16) of W_res in registers.
// Cross-CTA sync: tag-in-payload. Producer stores {h0,h1,tag=t+1,0} as STG.128;
// consumers poll the 16B group itself (tag visible => data visible; no fences).
__global__ __launch_bounds__(THREADS_ESN, 1) void k_esn(const float* __restrict__ Wres) {
    __shared__ __align__(16) float hsm[RES];
    __shared__ float parts[16][17];
    __shared__ __align__(16) float hout[16];

    int tid = threadIdx.x, w = tid >> 5, l = tid & 31;
    int cta = blockIdx.x;
    int row = l >> 1, half = l & 1;
    int grow = cta * ROWS_PER_CTA + row;     // global row this lane accumulates
    int outrow = cta * ROWS_PER_CTA + w;     // global row this warp outputs

    // Load this lane's 64 W_res weights as 32 packed f32x2 operands.
    unsigned long long wreg[32];
    {
        const ulonglong2* wp = reinterpret_cast<const ulonglong2*>(
            Wres + (size_t)grow * RES + w * 128 + half * 4);
#pragma unroll
        for (int j = 0; j < 16; j++) {
            ulonglong2 v = wp[j * 2];        // 16B at float offset j*8
            wreg[2 * j]     = v.x;
            wreg[2 * j + 1] = v.y;
        }
    }

    for (int i = tid; i < RES; i += THREADS_ESN) hsm[i] = 0.f;
    __syncthreads();

    for (int t = 0; t < T_STEPS; t++) {
        // prefetch this warp's G value early (independent of h)
        float gval = (l == 0) ? __ldg(&g_G[(size_t)outrow * T_STEPS + t]) : 0.f;

        // partial dot over this lane's 64 columns (packed f32x2)
        const ulonglong2* hp = reinterpret_cast<const ulonglong2*>(
            hsm + w * 128 + half * 4);
        unsigned long long acc0 = 0ull, acc1 = 0ull;
#pragma unroll
        for (int j = 0; j < 16; j++) {
            ulonglong2 hv = hp[j * 2];       // LDS.128, 2 distinct addrs/warp: conflict-free
            acc0 = ffma2(wreg[2 * j],     hv.x, acc0);
            acc1 = ffma2(wreg[2 * j + 1], hv.y, acc1);
        }
        float s = __uint_as_float((unsigned)acc0) +
                  __uint_as_float((unsigned)(acc0 >> 32)) +
                  __uint_as_float((unsigned)acc1) +
                  __uint_as_float((unsigned)(acc1 >> 32));
        s += __shfl_xor_sync(0xffffffffu, s, 1);        // combine the two halves
        if (half == 0) parts[row][w] = s;
        __syncthreads();

        // warp w reduces row w across the 16 warps' column blocks
        float v = (l < 16) ? parts[w][l] : 0.f;
#pragma unroll
        for (int o = 8; o; o >>= 1) v += __shfl_xor_sync(0xffffffffu, v, o);
        if (l == 0) hout[w] = tanhf(v + gval);
        __syncthreads();

        // ---- publish: 8 tagged 16B groups {h_{2j}, h_{2j+1}, t+1, 0} -------------
        unsigned int* bufp = g_buf[t & 1];
        if (tid < 8) {
            float2 hv = *reinterpret_cast<const float2*>(&hout[2 * tid]);
            unsigned int* p = bufp + (size_t)(cta * 8 + tid) * 4;
            asm volatile("st.global.cg.v4.u32 [%0], {%1,%2,%3,%4};"
                         :: "l"(p), "r"(__float_as_uint(hv.x)), "r"(__float_as_uint(hv.y)),
                            "r"((unsigned int)(t + 1)), "r"(0u) : "memory");
        }
        if (tid < 4) {   // stash full h for k_out (off critical path, plain store)
            float4 hv = *reinterpret_cast<const float4*>(&hout[4 * tid]);
            *reinterpret_cast<float4*>(g_H + (size_t)t * RES + cta * ROWS_PER_CTA + 4 * tid) = hv;
        }

        // ---- consume: poll 2 groups per thread until tag == t+1, scatter to smem --
        if (t + 1 < T_STEPS) {
            unsigned int tag = (unsigned int)(t + 1);
            const unsigned int* p0 = bufp + (size_t)tid * 4;
            const unsigned int* p1 = bufp + (size_t)(tid + 512) * 4;
            unsigned int a0, a1, a2, a3, b0, b1, b2, b3;
            bool d0 = false, d1 = false;
            do {
                if (!d0) {
                    asm volatile("ld.global.cg.v4.u32 {%0,%1,%2,%3},[%4];"
                                 : "=r"(a0), "=r"(a1), "=r"(a2), "=r"(a3) : "l"(p0));
                    d0 = (a2 == tag);
                }
                if (!d1) {
                    asm volatile("ld.global.cg.v4.u32 {%0,%1,%2,%3},[%4];"
                                 : "=r"(b0), "=r"(b1), "=r"(b2), "=r"(b3) : "l"(p1));
                    d1 = (b2 == tag);
                }
            } while (!(d0 && d1));
            // group g holds h[2g], h[2g+1]
            *reinterpret_cast<float2*>(hsm + 2 * tid) =
                make_float2(__uint_as_float(a0), __uint_as_float(a1));
            *reinterpret_cast<float2*>(hsm + 1024 + 2 * tid) =
                make_float2(__uint_as_float(b0), __uint_as_float(b1));
            __syncthreads();
        }
    }
}

// ---------------- kernel 4: y[t] = dW[0:64].U[t] + dW[64:].H[t] + b ------------------
__global__ __launch_bounds__(256) void k_out(const float* __restrict__ dW,
                                             const float* __restrict__ db,
                                             float* __restrict__ y) {
    int t = blockIdx.x, tid = threadIdx.x;
    float acc = 0.f;
    if (tid < 64) acc = dW[tid] * g_U[t * 64 + tid];
    for (int r = tid; r < RES; r += 256)
        acc = fmaf(dW[64 + r], g_H[(size_t)t * RES + r], acc);
#pragma unroll
    for (int o = 16; o; o >>= 1) acc += __shfl_xor_sync(0xffffffffu, acc, o);
    __shared__ float red[8];
    if ((tid & 31) == 0) red[tid >> 5] = acc;
    __syncthreads();
    if (tid < 8) {
        float v = red[tid];
        v += __shfl_xor_sync(0xffu, v, 4);
        v += __shfl_xor_sync(0xffu, v, 2);
        v += __shfl_xor_sync(0xffu, v, 1);
        if (tid == 0) y[t] = v + db[0];
    }
}

// ---------------- launcher ----------------------------------------------------------
extern "C" void kernel_launch(void* const* d_in, const int* in_sizes, int n_in,
                              void* d_out, int out_size) {
    const float* X    = (const float*)d_in[0];   // (4096, 64, 1)
    const float* C    = (const float*)d_in[1];   // (64, 64)
    const float* Win  = (const float*)d_in[2];   // (2048, 64)
    const float* Wres = (const float*)d_in[3];   // (2048, 2048)
    const float* dW   = (const float*)d_in[4];   // (1, 2112)
    const float* db   = (const float*)d_in[5];   // (1,)
    float* y = (float*)d_out;                    // (4096, 1, 1)

    k_u  <<<T_STEPS / 4, 256>>>(X, C);           // also zeroes g_buf tags
    k_g  <<<T_STEPS / 32, 512>>>(Win);
    k_esn<<<NCTA, THREADS_ESN>>>(Wres);
    k_out<<<T_STEPS, 256>>>(dW, db, y);
}